// round 2
// baseline (speedup 1.0000x reference)
#include <cuda_runtime.h>
#include <stdint.h>

// ---------------------------------------------------------------------------
// GATv2 layer collapses algebraically:
//   Vv_e = node_feats[dest_e] @ W_v + b_v  depends only on dest_e, and the
//   scatter-softmax weights alpha over each dest segment sum to 1. Hence
//   out[d] = (node_feats[d] @ W_v + b_v) * (node d has >=1 in-edge).
//
// NOTE: edge_index is int32 on device (JAX default x64-disabled silently
// downcasts jnp.int64 -> int32).
// ---------------------------------------------------------------------------

#define FLAG_CAP (1 << 20)
__device__ unsigned char g_flags[FLAG_CAP];  // zero-init at module load;
                                             // vproj_kernel resets to 0 so
                                             // graph replays stay deterministic.

// ---- packed f32x2 helpers (Blackwell FFMA2 path; PTX-only) ----------------
__device__ __forceinline__ unsigned long long dup2(float v) {
    unsigned long long r;
    asm("mov.b64 %0, {%1, %1};" : "=l"(r) : "f"(v));
    return r;
}
__device__ __forceinline__ void fma2(unsigned long long& d,
                                     unsigned long long a,
                                     unsigned long long b) {
    asm("fma.rn.f32x2 %0, %1, %2, %0;" : "+l"(d) : "l"(a), "l"(b));
}
__device__ __forceinline__ float2 unpack2(unsigned long long v) {
    float2 r;
    asm("mov.b64 {%0, %1}, %2;" : "=f"(r.x), "=f"(r.y) : "l"(v));
    return r;
}

// ---------------------------------------------------------------------------
// Kernel 1: mark destination nodes with >=1 in-edge. int32 indices, int4 loads.
// Benign same-value byte-store races; no atomics.
// ---------------------------------------------------------------------------
__global__ __launch_bounds__(256) void mark_kernel(
    const int* __restrict__ dest, int E, int V) {
    int i = (blockIdx.x * blockDim.x + threadIdx.x) * 4;
    if (i + 3 < E) {
        int4 d = *reinterpret_cast<const int4*>(dest + i);
        if ((unsigned)d.x < (unsigned)V) g_flags[d.x] = 1;
        if ((unsigned)d.y < (unsigned)V) g_flags[d.y] = 1;
        if ((unsigned)d.z < (unsigned)V) g_flags[d.z] = 1;
        if ((unsigned)d.w < (unsigned)V) g_flags[d.w] = 1;
    } else {
        for (int j = i; j < E; j++) {
            int a = dest[j];
            if ((unsigned)a < (unsigned)V) g_flags[a] = 1;
        }
    }
}

// ---------------------------------------------------------------------------
// Kernel 2: out[r][:] = flag[r] ? X[r] @ W + b : 0, then reset flag[r] = 0.
// Block = 256 threads, 128 rows/block, D = 64. X tile transposed in smem
// (stride 130) so consecutive rows form natural f32x2 pairs via LDS.64.
// Per thread: 8 rows (4 pairs) x 4 cols -> 16 FFMA2 per k.
// ---------------------------------------------------------------------------
#define TILE_R 128
#define XT_STRIDE 130

__global__ __launch_bounds__(256) void vproj_kernel(
    const float* __restrict__ X,     // [V,64]
    const float* __restrict__ Wv,    // [64,64]
    const float* __restrict__ bv,    // [64]
    float* __restrict__ out,         // [V,64]
    int V) {
    __shared__ __align__(16) float Ws[64 * 64];
    __shared__ __align__(16) float Xt[64 * XT_STRIDE];

    const int tid = threadIdx.x;
    const int r_base = blockIdx.x * TILE_R;

    // Load W (4096 floats) coalesced.
    {
        const float4* W4 = reinterpret_cast<const float4*>(Wv);
        float4* Ws4 = reinterpret_cast<float4*>(Ws);
#pragma unroll
        for (int i = 0; i < 4; i++) Ws4[tid + i * 256] = W4[tid + i * 256];
    }

    // Load X tile [128 rows x 64 cols] transposed into Xt[k][row].
    {
        const float4* X4 = reinterpret_cast<const float4*>(X);
#pragma unroll
        for (int i = 0; i < 8; i++) {
            int c = tid + i * 256;          // 2048 float4 chunks
            int row = c >> 4;               // 0..127
            int kq = (c & 15) << 2;         // 0,4,...,60
            int grow = r_base + row;
            float4 v = make_float4(0.f, 0.f, 0.f, 0.f);
            if (grow < V) v = X4[grow * 16 + (c & 15)];
            Xt[(kq + 0) * XT_STRIDE + row] = v.x;
            Xt[(kq + 1) * XT_STRIDE + row] = v.y;
            Xt[(kq + 2) * XT_STRIDE + row] = v.z;
            Xt[(kq + 3) * XT_STRIDE + row] = v.w;
        }
    }
    __syncthreads();

    const int j0 = (tid & 15) * 4;   // output column group
    const int r0 = (tid >> 4) * 8;   // local row group (8 rows = 4 pairs)

    unsigned long long acc[4][4];
#pragma unroll
    for (int p = 0; p < 4; p++)
#pragma unroll
        for (int c = 0; c < 4; c++) acc[p][c] = 0ULL;

#pragma unroll 16
    for (int k = 0; k < 64; k++) {
        const float4 w4 = *reinterpret_cast<const float4*>(&Ws[(k << 6) + j0]);
        unsigned long long wd0 = dup2(w4.x);
        unsigned long long wd1 = dup2(w4.y);
        unsigned long long wd2 = dup2(w4.z);
        unsigned long long wd3 = dup2(w4.w);
        const unsigned long long* xp =
            reinterpret_cast<const unsigned long long*>(&Xt[k * XT_STRIDE + r0]);
        unsigned long long xa = xp[0];
        unsigned long long xb = xp[1];
        unsigned long long xc = xp[2];
        unsigned long long xd = xp[3];
        fma2(acc[0][0], xa, wd0); fma2(acc[0][1], xa, wd1);
        fma2(acc[0][2], xa, wd2); fma2(acc[0][3], xa, wd3);
        fma2(acc[1][0], xb, wd0); fma2(acc[1][1], xb, wd1);
        fma2(acc[1][2], xb, wd2); fma2(acc[1][3], xb, wd3);
        fma2(acc[2][0], xc, wd0); fma2(acc[2][1], xc, wd1);
        fma2(acc[2][2], xc, wd2); fma2(acc[2][3], xc, wd3);
        fma2(acc[3][0], xd, wd0); fma2(acc[3][1], xd, wd1);
        fma2(acc[3][2], xd, wd2); fma2(acc[3][3], xd, wd3);
    }

    // Epilogue: add bias, apply in-edge mask, store.
    const float4 b4 = *reinterpret_cast<const float4*>(&bv[j0]);
#pragma unroll
    for (int p = 0; p < 4; p++) {
        float2 c0 = unpack2(acc[p][0]);
        float2 c1 = unpack2(acc[p][1]);
        float2 c2 = unpack2(acc[p][2]);
        float2 c3 = unpack2(acc[p][3]);
        int g0 = r_base + r0 + 2 * p;
        int g1 = g0 + 1;
        if (g0 < V) {
            float f = g_flags[g0] ? 1.0f : 0.0f;
            float4 o = make_float4((c0.x + b4.x) * f, (c1.x + b4.y) * f,
                                   (c2.x + b4.z) * f, (c3.x + b4.w) * f);
            *reinterpret_cast<float4*>(&out[g0 * 64 + j0]) = o;
        }
        if (g1 < V) {
            float f = g_flags[g1] ? 1.0f : 0.0f;
            float4 o = make_float4((c0.y + b4.x) * f, (c1.y + b4.y) * f,
                                   (c2.y + b4.z) * f, (c3.y + b4.w) * f);
            *reinterpret_cast<float4*>(&out[g1 * 64 + j0]) = o;
        }
    }

    // Reset flags for this block's rows (restores all-zero invariant so the
    // captured graph is replayable). All reads of g_flags happened above.
    __syncthreads();
    for (int r = tid; r < TILE_R; r += 256) {
        int g = r_base + r;
        if (g < V) g_flags[g] = 0;
    }
}

// ---------------------------------------------------------------------------
extern "C" void kernel_launch(void* const* d_in, const int* in_sizes, int n_in,
                              void* d_out, int out_size) {
    const float* node_feats = (const float*)d_in[0];
    const int* edge_index = (const int*)d_in[2];   // int32! (JAX x64 disabled)
    const float* W_v = (const float*)d_in[7];
    const float* b_v = (const float*)d_in[8];
    float* out = (float*)d_out;

    const int V = in_sizes[0] / 64;
    const int E = in_sizes[2] / 2;
    const int* dest = edge_index + E;  // edge_index[1]

    {
        int threads = 256;
        int work = (E + 3) / 4;
        int blocks = (work + threads - 1) / threads;
        mark_kernel<<<blocks, threads>>>(dest, E, V);
    }
    {
        int blocks = (V + TILE_R - 1) / TILE_R;
        vproj_kernel<<<blocks, 256>>>(node_feats, W_v, b_v, out, V);
    }
}